// round 2
// baseline (speedup 1.0000x reference)
#include <cuda_runtime.h>

#define N_NODES 50000
#define N_EDGES 1600000
#define E_TOT   (N_EDGES + N_NODES)

// ---------------- scratch (device globals; no allocation allowed) ----------
__device__ float4 g_Wn[N_NODES * 16];     // projected node features [N,64] as float4
__device__ float4 g_dotS[N_NODES];        // a_s . Wn[n]  per head
__device__ float4 g_dotR[N_NODES];        // a_r . Wn[n]  per head
__device__ float4 g_norm[N_NODES];        // softmax denominator per head
__device__ float4 g_aggr[N_NODES * 16];   // weighted sum [N,64]
__device__ float  g_ce[64];               // c_e[h*16+i] = sum_f a_e[h,f]*W_edge[h,f,i]

// vector reduction: 4x fewer REDG instructions than scalar atomicAdd
__device__ __forceinline__ void red_add_v4(float4* addr, float x, float y, float z, float w) {
    asm volatile("red.global.add.v4.f32 [%0], {%1, %2, %3, %4};"
                 :: "l"(addr), "f"(x), "f"(y), "f"(z), "f"(w) : "memory");
}

// ---------------- K0: fold a_e into W_edge -> c_e ---------------------------
__global__ void k_ce(const float* __restrict__ a, const float* __restrict__ We) {
    int t = threadIdx.x;             // 64 threads
    int h = t >> 4, i = t & 15;
    float acc = 0.f;
#pragma unroll
    for (int f = 0; f < 16; f++)
        acc += a[h * 48 + 32 + f] * We[h * 256 + f * 16 + i];
    g_ce[t] = acc;
}

// ---------------- K1: zero accumulators -------------------------------------
__global__ void k_init() {
    int i = blockIdx.x * blockDim.x + threadIdx.x;   // grid covers N*16 exactly
    float4 z = make_float4(0.f, 0.f, 0.f, 0.f);
    if (i < N_NODES) g_norm[i] = z;
    if (i < N_NODES * 16) g_aggr[i] = z;
}

// ---------------- K2: node projection + logit dots --------------------------
// warp per node; W transposed in smem (padded, conflict-free)
__global__ void k_node(const float* __restrict__ nodes,
                       const float* __restrict__ W,
                       const float* __restrict__ a) {
    __shared__ float sWt[64 * 65];          // sWt[i*65 + j] = W[j*64 + i]
    __shared__ float sA[192];
    __shared__ float sNode[8][64];

    int tid = threadIdx.x;
    for (int idx = tid; idx < 4096; idx += 256) {
        int j = idx >> 6, i = idx & 63;
        sWt[i * 65 + j] = W[idx];
    }
    if (tid < 192) sA[tid] = a[tid];
    __syncthreads();

    int warp = tid >> 5, lane = tid & 31;
    float* wn = (float*)g_Wn;
    float* dS = (float*)g_dotS;
    float* dR = (float*)g_dotR;

    for (int node = blockIdx.x * 8 + warp; node < N_NODES; node += gridDim.x * 8) {
        const float* nr = nodes + (size_t)node * 64;
        sNode[warp][lane]      = nr[lane];
        sNode[warp][lane + 32] = nr[lane + 32];
        __syncwarp();

        int j0 = lane, j1 = lane + 32;
        float acc0 = 0.f, acc1 = 0.f;
#pragma unroll
        for (int i = 0; i < 64; i++) {
            float nv = sNode[warp][i];
            acc0 += sWt[i * 65 + j0] * nv;
            acc1 += sWt[i * 65 + j1] * nv;
        }
        wn[(size_t)node * 64 + j0] = acc0;
        wn[(size_t)node * 64 + j1] = acc1;

        // per-head dots with a_s / a_r
        int h0 = lane >> 4, f = lane & 15;
        int h1 = h0 + 2;
        float ps = acc0 * sA[h0 * 48 + f];
        float pr = acc0 * sA[h0 * 48 + 16 + f];
        float qs = acc1 * sA[h1 * 48 + f];
        float qr = acc1 * sA[h1 * 48 + 16 + f];
#pragma unroll
        for (int m = 8; m >= 1; m >>= 1) {
            ps += __shfl_xor_sync(0xffffffffu, ps, m, 16);
            pr += __shfl_xor_sync(0xffffffffu, pr, m, 16);
            qs += __shfl_xor_sync(0xffffffffu, qs, m, 16);
            qr += __shfl_xor_sync(0xffffffffu, qr, m, 16);
        }
        if (f == 0) {
            dS[node * 4 + h0] = ps;  dS[node * 4 + h1] = qs;
            dR[node * 4 + h0] = pr;  dR[node * 4 + h1] = qr;
        }
        __syncwarp();
    }
}

// ---------------- K3: fused edge pass ---------------------------------------
// per edge: logit -> leaky -> exp -> red norm[r], red aggr[r] += w * Wn[s]
__global__ void k_edge(const float* __restrict__ edges,
                       const int* __restrict__ recv,
                       const int* __restrict__ send) {
    __shared__ float sce[64];
    if (threadIdx.x < 64) sce[threadIdx.x] = g_ce[threadIdx.x];
    __syncthreads();

    int e = blockIdx.x * 256 + threadIdx.x;
    if (e >= E_TOT) return;

    int s, r;
    float m0, m1, m2, m3;
    if (e < N_EDGES) {
        s = send[e];
        r = recv[e];
        float4 ds = g_dotS[s];
        float4 dr = g_dotR[r];
        const float4* er = (const float4*)(edges + (size_t)e * 16);
        float4 e0 = er[0], e1 = er[1], e2 = er[2], e3 = er[3];
        float msg[4];
#pragma unroll
        for (int h = 0; h < 4; h++) {
            const float* c = sce + h * 16;
            msg[h] = e0.x * c[0]  + e0.y * c[1]  + e0.z * c[2]  + e0.w * c[3]
                   + e1.x * c[4]  + e1.y * c[5]  + e1.z * c[6]  + e1.w * c[7]
                   + e2.x * c[8]  + e2.y * c[9]  + e2.z * c[10] + e2.w * c[11]
                   + e3.x * c[12] + e3.y * c[13] + e3.z * c[14] + e3.w * c[15];
        }
        m0 = ds.x + dr.x + msg[0];
        m1 = ds.y + dr.y + msg[1];
        m2 = ds.z + dr.z + msg[2];
        m3 = ds.w + dr.w + msg[3];
    } else {
        int n = e - N_EDGES;        // self edge (edge features are zero)
        s = n; r = n;
        float4 ds = g_dotS[n];
        float4 dr = g_dotR[n];
        m0 = ds.x + dr.x;  m1 = ds.y + dr.y;
        m2 = ds.z + dr.z;  m3 = ds.w + dr.w;
    }

    // leaky_relu(0.01) then exp  (no max-shift needed: |logit| << 88)
    float w0 = __expf(m0 > 0.f ? m0 : 0.01f * m0);
    float w1 = __expf(m1 > 0.f ? m1 : 0.01f * m1);
    float w2 = __expf(m2 > 0.f ? m2 : 0.01f * m2);
    float w3 = __expf(m3 > 0.f ? m3 : 0.01f * m3);

    red_add_v4(&g_norm[r], w0, w1, w2, w3);

    const float4* wn = g_Wn + (size_t)s * 16;
    float4* ag = g_aggr + (size_t)r * 16;
    float wh[4] = {w0, w1, w2, w3};
#pragma unroll
    for (int k = 0; k < 16; k++) {
        float4 v = wn[k];
        float w = wh[k >> 2];
        red_add_v4(&ag[k], v.x * w, v.y * w, v.z * w, v.w * w);
    }
}

// ---------------- K4: normalize + ELU + LayerNorm ---------------------------
__global__ void k_final(const float* __restrict__ scale,
                        const float* __restrict__ bias,
                        float* __restrict__ out) {
    int warp = threadIdx.x >> 5, lane = threadIdx.x & 31;
    int node = blockIdx.x * 8 + warp;
    if (node >= N_NODES) return;

    const float* ag = (const float*)(g_aggr + (size_t)node * 16);
    const float* nm = (const float*)&g_norm[node];

    int j0 = lane, j1 = lane + 32;
    float x0 = ag[j0] / nm[j0 >> 4];
    float x1 = ag[j1] / nm[j1 >> 4];
    float y0 = x0 > 0.f ? x0 : expm1f(x0);   // ELU(alpha=1)
    float y1 = x1 > 0.f ? x1 : expm1f(x1);

    float sum = y0 + y1;
#pragma unroll
    for (int m = 16; m >= 1; m >>= 1) sum += __shfl_xor_sync(0xffffffffu, sum, m);
    float mean = sum * (1.0f / 64.0f);

    float d0 = y0 - mean, d1 = y1 - mean;
    float v = d0 * d0 + d1 * d1;
#pragma unroll
    for (int m = 16; m >= 1; m >>= 1) v += __shfl_xor_sync(0xffffffffu, v, m);
    float inv = rsqrtf(v * (1.0f / 64.0f) + 1e-6f);

    out[(size_t)node * 64 + j0] = d0 * inv * scale[j0] + bias[j0];
    out[(size_t)node * 64 + j1] = d1 * inv * scale[j1] + bias[j1];
}

// ---------------- launch -----------------------------------------------------
extern "C" void kernel_launch(void* const* d_in, const int* in_sizes, int n_in,
                              void* d_out, int out_size) {
    const float* nodes   = (const float*)d_in[0];
    const float* edges   = (const float*)d_in[1];
    const int*   recv    = (const int*)d_in[2];
    const int*   send    = (const int*)d_in[3];
    const float* W       = (const float*)d_in[4];
    const float* W_edge  = (const float*)d_in[5];
    const float* a       = (const float*)d_in[6];
    const float* ln_s    = (const float*)d_in[7];
    const float* ln_b    = (const float*)d_in[8];
    float* out = (float*)d_out;

    k_ce<<<1, 64>>>(a, W_edge);
    k_init<<<(N_NODES * 16 + 255) / 256, 256>>>();
    k_node<<<625, 256>>>(nodes, W, a);
    k_edge<<<(E_TOT + 255) / 256, 256>>>(edges, recv, send);
    k_final<<<(N_NODES + 7) / 8, 256>>>(ln_s, ln_b, out);
}

// round 3
// speedup vs baseline: 1.4275x; 1.4275x over previous
#include <cuda_runtime.h>

#define N_NODES 50000
#define N_EDGES 1600000
#define E_TOT   (N_EDGES + N_NODES)

// ---------------- scratch (device globals; no allocation allowed) ----------
__device__ float4 g_Wn[N_NODES * 16];     // projected node features [N,64] as float4
__device__ float4 g_dotS[N_NODES];        // a_s . Wn[n]  per head
__device__ float4 g_dotR[N_NODES];        // a_r . Wn[n]  per head
__device__ float4 g_norm[N_NODES];        // softmax denominator per head
__device__ float4 g_aggr[N_NODES * 16];   // weighted sum [N,64]
__device__ float  g_ce[64];               // c_e[h*16+i] = sum_f a_e[h,f]*W_edge[h,f,i]

// vector reduction: 4x fewer REDG instructions than scalar atomicAdd
__device__ __forceinline__ void red_add_v4(float4* addr, float x, float y, float z, float w) {
    asm volatile("red.global.add.v4.f32 [%0], {%1, %2, %3, %4};"
                 :: "l"(addr), "f"(x), "f"(y), "f"(z), "f"(w) : "memory");
}

// ---------------- K0: fold a_e into W_edge -> c_e ---------------------------
__global__ void k_ce(const float* __restrict__ a, const float* __restrict__ We) {
    int t = threadIdx.x;             // 64 threads
    int h = t >> 4, i = t & 15;
    float acc = 0.f;
#pragma unroll
    for (int f = 0; f < 16; f++)
        acc += a[h * 48 + 32 + f] * We[h * 256 + f * 16 + i];
    g_ce[t] = acc;
}

// ---------------- K1: zero accumulators -------------------------------------
__global__ void k_init() {
    int i = blockIdx.x * blockDim.x + threadIdx.x;
    float4 z = make_float4(0.f, 0.f, 0.f, 0.f);
    if (i < N_NODES) g_norm[i] = z;
    if (i < N_NODES * 16) g_aggr[i] = z;
}

// ---------------- K2: node projection + logit dots --------------------------
// warp per node; W transposed in smem (padded, conflict-free)
__global__ void k_node(const float* __restrict__ nodes,
                       const float* __restrict__ W,
                       const float* __restrict__ a) {
    __shared__ float sWt[64 * 65];          // sWt[i*65 + j] = W[j*64 + i]
    __shared__ float sA[192];
    __shared__ float sNode[8][64];

    int tid = threadIdx.x;
    for (int idx = tid; idx < 4096; idx += 256) {
        int j = idx >> 6, i = idx & 63;
        sWt[i * 65 + j] = W[idx];
    }
    if (tid < 192) sA[tid] = a[tid];
    __syncthreads();

    int warp = tid >> 5, lane = tid & 31;
    float* wn = (float*)g_Wn;
    float* dS = (float*)g_dotS;
    float* dR = (float*)g_dotR;

    for (int node = blockIdx.x * 8 + warp; node < N_NODES; node += gridDim.x * 8) {
        const float* nr = nodes + (size_t)node * 64;
        sNode[warp][lane]      = nr[lane];
        sNode[warp][lane + 32] = nr[lane + 32];
        __syncwarp();

        int j0 = lane, j1 = lane + 32;
        float acc0 = 0.f, acc1 = 0.f;
#pragma unroll
        for (int i = 0; i < 64; i++) {
            float nv = sNode[warp][i];
            acc0 += sWt[i * 65 + j0] * nv;
            acc1 += sWt[i * 65 + j1] * nv;
        }
        wn[(size_t)node * 64 + j0] = acc0;
        wn[(size_t)node * 64 + j1] = acc1;

        // per-head dots with a_s / a_r
        int h0 = lane >> 4, f = lane & 15;
        int h1 = h0 + 2;
        float ps = acc0 * sA[h0 * 48 + f];
        float pr = acc0 * sA[h0 * 48 + 16 + f];
        float qs = acc1 * sA[h1 * 48 + f];
        float qr = acc1 * sA[h1 * 48 + 16 + f];
#pragma unroll
        for (int m = 8; m >= 1; m >>= 1) {
            ps += __shfl_xor_sync(0xffffffffu, ps, m, 16);
            pr += __shfl_xor_sync(0xffffffffu, pr, m, 16);
            qs += __shfl_xor_sync(0xffffffffu, qs, m, 16);
            qr += __shfl_xor_sync(0xffffffffu, qr, m, 16);
        }
        if (f == 0) {
            dS[node * 4 + h0] = ps;  dS[node * 4 + h1] = qs;
            dR[node * 4 + h0] = pr;  dR[node * 4 + h1] = qr;
        }
        __syncwarp();
    }
}

// ---------------- K3: fused edge pass (warp-cooperative, coalesced) ----------
// 16 lanes per edge, 2 edges per warp. All wide accesses (edge features,
// Wn[s] gather, aggr[r] scatter-red) are lane-contiguous -> ~5x fewer L1
// wavefronts than the thread-per-edge version.
// E_TOT = 1,650,000 = 103,125 blocks * 8 warps * 2 edges exactly (no tail).
__global__ void __launch_bounds__(256) k_edge(const float* __restrict__ edges,
                                              const int* __restrict__ recv,
                                              const int* __restrict__ send) {
    __shared__ float sce[64];
    if (threadIdx.x < 64) sce[threadIdx.x] = g_ce[threadIdx.x];
    __syncthreads();

    int lane = threadIdx.x & 31;
    int half = lane >> 4;                    // which edge of this warp
    int sub  = lane & 15;                    // lane within the edge's 16-group
    int e = (blockIdx.x * 8 + (threadIdx.x >> 5)) * 2 + half;

    int s, r;
    float ef;
    if (e < N_EDGES) {
        s  = send[e];
        r  = recv[e];
        ef = edges[(size_t)e * 16 + sub];    // 16 lanes x 4B contiguous
    } else {
        s = r = e - N_EDGES;                 // self edge, zero features
        ef = 0.f;
    }

    // logit edge-term: dot(e, c_h) reduced across the 16-lane group
    float p0 = ef * sce[sub];
    float p1 = ef * sce[16 + sub];
    float p2 = ef * sce[32 + sub];
    float p3 = ef * sce[48 + sub];
#pragma unroll
    for (int m = 8; m >= 1; m >>= 1) {
        p0 += __shfl_xor_sync(0xffffffffu, p0, m, 16);
        p1 += __shfl_xor_sync(0xffffffffu, p1, m, 16);
        p2 += __shfl_xor_sync(0xffffffffu, p2, m, 16);
        p3 += __shfl_xor_sync(0xffffffffu, p3, m, 16);
    }

    float4 ds = g_dotS[s];                   // broadcast within 16-lane group
    float4 dr = g_dotR[r];
    float m0 = ds.x + dr.x + p0;
    float m1 = ds.y + dr.y + p1;
    float m2 = ds.z + dr.z + p2;
    float m3 = ds.w + dr.w + p3;

    // leaky_relu(0.01) then exp (no max-shift needed: |logit| << 88)
    float w0 = __expf(m0 > 0.f ? m0 : 0.01f * m0);
    float w1 = __expf(m1 > 0.f ? m1 : 0.01f * m1);
    float w2 = __expf(m2 > 0.f ? m2 : 0.01f * m2);
    float w3 = __expf(m3 > 0.f ? m3 : 0.01f * m3);

    if (sub == 0) red_add_v4(&g_norm[r], w0, w1, w2, w3);

    // lane sub covers output floats [4*sub, 4*sub+3]; head = sub>>2
    float4 v = g_Wn[s * 16 + sub];           // 16 lanes x 16B contiguous (2 lines)
    float w = (sub < 8) ? (sub < 4 ? w0 : w1) : (sub < 12 ? w2 : w3);
    red_add_v4(&g_aggr[r * 16 + sub], v.x * w, v.y * w, v.z * w, v.w * w);
}

// ---------------- K4: normalize + ELU + LayerNorm ---------------------------
__global__ void k_final(const float* __restrict__ scale,
                        const float* __restrict__ bias,
                        float* __restrict__ out) {
    int warp = threadIdx.x >> 5, lane = threadIdx.x & 31;
    int node = blockIdx.x * 8 + warp;
    if (node >= N_NODES) return;

    const float* ag = (const float*)(g_aggr + (size_t)node * 16);
    const float* nm = (const float*)&g_norm[node];

    int j0 = lane, j1 = lane + 32;
    float x0 = ag[j0] / nm[j0 >> 4];
    float x1 = ag[j1] / nm[j1 >> 4];
    float y0 = x0 > 0.f ? x0 : expm1f(x0);   // ELU(alpha=1)
    float y1 = x1 > 0.f ? x1 : expm1f(x1);

    float sum = y0 + y1;
#pragma unroll
    for (int m = 16; m >= 1; m >>= 1) sum += __shfl_xor_sync(0xffffffffu, sum, m);
    float mean = sum * (1.0f / 64.0f);

    float d0 = y0 - mean, d1 = y1 - mean;
    float v = d0 * d0 + d1 * d1;
#pragma unroll
    for (int m = 16; m >= 1; m >>= 1) v += __shfl_xor_sync(0xffffffffu, v, m);
    float inv = rsqrtf(v * (1.0f / 64.0f) + 1e-6f);

    out[(size_t)node * 64 + j0] = d0 * inv * scale[j0] + bias[j0];
    out[(size_t)node * 64 + j1] = d1 * inv * scale[j1] + bias[j1];
}

// ---------------- launch -----------------------------------------------------
extern "C" void kernel_launch(void* const* d_in, const int* in_sizes, int n_in,
                              void* d_out, int out_size) {
    const float* nodes   = (const float*)d_in[0];
    const float* edges   = (const float*)d_in[1];
    const int*   recv    = (const int*)d_in[2];
    const int*   send    = (const int*)d_in[3];
    const float* W       = (const float*)d_in[4];
    const float* W_edge  = (const float*)d_in[5];
    const float* a       = (const float*)d_in[6];
    const float* ln_s    = (const float*)d_in[7];
    const float* ln_b    = (const float*)d_in[8];
    float* out = (float*)d_out;

    k_ce<<<1, 64>>>(a, W_edge);
    k_init<<<(N_NODES * 16 + 255) / 256, 256>>>();
    k_node<<<625, 256>>>(nodes, W, a);
    k_edge<<<E_TOT / 16, 256>>>(edges, recv, send);   // 103,125 blocks, exact
    k_final<<<(N_NODES + 7) / 8, 256>>>(ln_s, ln_b, out);
}

// round 6
// speedup vs baseline: 1.6340x; 1.1447x over previous
#include <cuda_runtime.h>

#define N_NODES 50000
#define N_EDGES 1600000
#define E_TOT   (N_EDGES + N_NODES)

// ---------------- scratch (device globals; no allocation allowed) ----------
__device__ float4 g_Wn[N_NODES * 16];     // projected node features [N,64] as float4
__device__ float4 g_dotS[N_NODES];        // a_s . Wn[n]  per head
__device__ float4 g_dotR[N_NODES];        // a_r . Wn[n]  per head
__device__ float4 g_norm[N_NODES];        // softmax denominator per head
__device__ float4 g_aggr[N_NODES * 16];   // weighted sum [N,64]
__device__ float4 g_ce4[16];              // c_e as float4: g_ce4[h*4+q] = c_h[4q..4q+3]

// vector reduction: 4x fewer REDG instructions than scalar atomicAdd
__device__ __forceinline__ void red_add_v4(float4* addr, float x, float y, float z, float w) {
    asm volatile("red.global.add.v4.f32 [%0], {%1, %2, %3, %4};"
                 :: "l"(addr), "f"(x), "f"(y), "f"(z), "f"(w) : "memory");
}
__device__ __forceinline__ void red_add_f32(float* addr, float v) {
    asm volatile("red.global.add.f32 [%0], %1;" :: "l"(addr), "f"(v) : "memory");
}

// ---------------- K0: fold a_e into W_edge -> c_e ---------------------------
__global__ void k_ce(const float* __restrict__ a, const float* __restrict__ We) {
    int t = threadIdx.x;             // 64 threads; t = h*16 + i
    int h = t >> 4, i = t & 15;
    float acc = 0.f;
#pragma unroll
    for (int f = 0; f < 16; f++)
        acc += a[h * 48 + 32 + f] * We[h * 256 + f * 16 + i];
    ((float*)g_ce4)[t] = acc;
}

// ---------------- K1: zero accumulators -------------------------------------
__global__ void k_init() {
    int i = blockIdx.x * blockDim.x + threadIdx.x;
    float4 z = make_float4(0.f, 0.f, 0.f, 0.f);
    if (i < N_NODES) g_norm[i] = z;
    if (i < N_NODES * 16) g_aggr[i] = z;
}

// ---------------- K2: node projection + logit dots --------------------------
__global__ void k_node(const float* __restrict__ nodes,
                       const float* __restrict__ W,
                       const float* __restrict__ a) {
    __shared__ float sWt[64 * 65];          // sWt[i*65 + j] = W[j*64 + i]
    __shared__ float sA[192];
    __shared__ float sNode[8][64];

    int tid = threadIdx.x;
    for (int idx = tid; idx < 4096; idx += 256) {
        int j = idx >> 6, i = idx & 63;
        sWt[i * 65 + j] = W[idx];
    }
    if (tid < 192) sA[tid] = a[tid];
    __syncthreads();

    int warp = tid >> 5, lane = tid & 31;
    float* wn = (float*)g_Wn;
    float* dS = (float*)g_dotS;
    float* dR = (float*)g_dotR;

    for (int node = blockIdx.x * 8 + warp; node < N_NODES; node += gridDim.x * 8) {
        const float* nr = nodes + (size_t)node * 64;
        sNode[warp][lane]      = nr[lane];
        sNode[warp][lane + 32] = nr[lane + 32];
        __syncwarp();

        int j0 = lane, j1 = lane + 32;
        float acc0 = 0.f, acc1 = 0.f;
#pragma unroll
        for (int i = 0; i < 64; i++) {
            float nv = sNode[warp][i];
            acc0 += sWt[i * 65 + j0] * nv;
            acc1 += sWt[i * 65 + j1] * nv;
        }
        wn[(size_t)node * 64 + j0] = acc0;
        wn[(size_t)node * 64 + j1] = acc1;

        int h0 = lane >> 4, f = lane & 15;
        int h1 = h0 + 2;
        float ps = acc0 * sA[h0 * 48 + f];
        float pr = acc0 * sA[h0 * 48 + 16 + f];
        float qs = acc1 * sA[h1 * 48 + f];
        float qr = acc1 * sA[h1 * 48 + 16 + f];
#pragma unroll
        for (int m = 8; m >= 1; m >>= 1) {
            ps += __shfl_xor_sync(0xffffffffu, ps, m, 16);
            pr += __shfl_xor_sync(0xffffffffu, pr, m, 16);
            qs += __shfl_xor_sync(0xffffffffu, qs, m, 16);
            qr += __shfl_xor_sync(0xffffffffu, qr, m, 16);
        }
        if (f == 0) {
            dS[node * 4 + h0] = ps;  dS[node * 4 + h1] = qs;
            dR[node * 4 + h0] = pr;  dR[node * 4 + h1] = qr;
        }
        __syncwarp();
    }
}

// ---------------- K3: fused edge pass (quad-dot, 2 shuffles, 1 exp) ----------
// 16 lanes per edge, 2 edges per warp. Lane sub owns head h=sub>>2 and
// feature-quad q=sub&3: float4 edge load (row still fully coalesced across the
// 16 lanes), 4 FMAs vs preloaded c_h[4q..4q+3], then a 2-round width-4
// shuffle reduce within the quad. Every lane ends with its OWN head's logit:
// no cross-head selection, one exp per lane.
// E_TOT = 1,650,000 = 103,125 blocks * 8 warps * 2 edges exactly (no tail).
__global__ void __launch_bounds__(256) k_edge(const float* __restrict__ edges,
                                              const int* __restrict__ recv,
                                              const int* __restrict__ send) {
    int lane = threadIdx.x & 31;
    int sub  = lane & 15;                    // lane within the edge's 16-group
    int h    = sub >> 2;                     // this lane's head
    int q    = sub & 3;                      // this lane's feature quad
    int e = (blockIdx.x * 8 + (threadIdx.x >> 5)) * 2 + (lane >> 4);

    float4 c4 = g_ce4[sub];                  // c_h[4q..4q+3] (L1/L2 broadcast)

    int s, r;
    float p;
    if (e < N_EDGES) {
        s = send[e];                         // broadcast within 16-lane group
        r = recv[e];
        float4 ef = ((const float4*)edges)[(size_t)e * 4 + q];  // 64B row, coalesced
        p = ef.x * c4.x + ef.y * c4.y + ef.z * c4.z + ef.w * c4.w;
    } else {
        s = r = e - N_EDGES;                 // self edge, zero features
        p = 0.f;
    }

    // reduce over the 4-lane quad: everyone in the quad gets head-h's edge dot
    p += __shfl_xor_sync(0xffffffffu, p, 1, 4);
    p += __shfl_xor_sync(0xffffffffu, p, 2, 4);

    const float* dSf = (const float*)g_dotS;
    const float* dRf = (const float*)g_dotR;
    float m = dSf[s * 4 + h] + dRf[r * 4 + h] + p;
    float w = __expf(m > 0.f ? m : 0.01f * m);   // leaky(0.01) then exp; |logit| << 88

    // softmax denominator: one lane per head (4 lanes hit the same 16B line)
    if (q == 0) red_add_f32((float*)&g_norm[r] + h, w);

    // lane sub covers output floats [4*sub, 4*sub+3]
    float4 v = g_Wn[s * 16 + sub];               // 16B x 16 lanes contiguous
    red_add_v4(&g_aggr[r * 16 + sub], v.x * w, v.y * w, v.z * w, v.w * w);
}

// ---------------- K4: normalize + ELU + LayerNorm ---------------------------
__global__ void k_final(const float* __restrict__ scale,
                        const float* __restrict__ bias,
                        float* __restrict__ out) {
    int warp = threadIdx.x >> 5, lane = threadIdx.x & 31;
    int node = blockIdx.x * 8 + warp;
    if (node >= N_NODES) return;

    const float* ag = (const float*)(g_aggr + (size_t)node * 16);
    const float* nm = (const float*)&g_norm[node];

    int j0 = lane, j1 = lane + 32;
    float x0 = ag[j0] / nm[j0 >> 4];
    float x1 = ag[j1] / nm[j1 >> 4];
    float y0 = x0 > 0.f ? x0 : expm1f(x0);   // ELU(alpha=1)
    float y1 = x1 > 0.f ? x1 : expm1f(x1);

    float sum = y0 + y1;
#pragma unroll
    for (int m = 16; m >= 1; m >>= 1) sum += __shfl_xor_sync(0xffffffffu, sum, m);
    float mean = sum * (1.0f / 64.0f);

    float d0 = y0 - mean, d1 = y1 - mean;
    float v = d0 * d0 + d1 * d1;
#pragma unroll
    for (int m = 16; m >= 1; m >>= 1) v += __shfl_xor_sync(0xffffffffu, v, m);
    float inv = rsqrtf(v * (1.0f / 64.0f) + 1e-6f);

    out[(size_t)node * 64 + j0] = d0 * inv * scale[j0] + bias[j0];
    out[(size_t)node * 64 + j1] = d1 * inv * scale[j1] + bias[j1];
}

// ---------------- launch -----------------------------------------------------
extern "C" void kernel_launch(void* const* d_in, const int* in_sizes, int n_in,
                              void* d_out, int out_size) {
    const float* nodes   = (const float*)d_in[0];
    const float* edges   = (const float*)d_in[1];
    const int*   recv    = (const int*)d_in[2];
    const int*   send    = (const int*)d_in[3];
    const float* W       = (const float*)d_in[4];
    const float* W_edge  = (const float*)d_in[5];
    const float* a       = (const float*)d_in[6];
    const float* ln_s    = (const float*)d_in[7];
    const float* ln_b    = (const float*)d_in[8];
    float* out = (float*)d_out;

    k_ce<<<1, 64>>>(a, W_edge);
    k_init<<<(N_NODES * 16 + 255) / 256, 256>>>();
    k_node<<<625, 256>>>(nodes, W, a);
    k_edge<<<E_TOT / 16, 256>>>(edges, recv, send);   // 103,125 blocks, exact
    k_final<<<(N_NODES + 7) / 8, 256>>>(ln_s, ln_b, out);
}

// round 7
// speedup vs baseline: 1.9456x; 1.1907x over previous
#include <cuda_runtime.h>

#define N_NODES 50000
#define N_EDGES 1600000
#define E_TOT   (N_EDGES + N_NODES)

// ---------------- scratch (device globals; no allocation allowed) ----------
__device__ float4 g_Wn[N_NODES * 16];     // projected node features [N,64] as float4
__device__ float4 g_dotS[N_NODES];        // a_s . Wn[n]  per head
__device__ float4 g_dotR[N_NODES];        // a_r . Wn[n]  per head
__device__ float4 g_norm[N_NODES];        // softmax denominator per head
__device__ float4 g_aggr[N_NODES * 16];   // weighted sum [N,64]
__device__ float4 g_ce4[16];              // c_e as float4: g_ce4[h*4+q] = c_h[4q..4q+3]

__device__ __forceinline__ void red_add_v4(float4* addr, float x, float y, float z, float w) {
    asm volatile("red.global.add.v4.f32 [%0], {%1, %2, %3, %4};"
                 :: "l"(addr), "f"(x), "f"(y), "f"(z), "f"(w) : "memory");
}
__device__ __forceinline__ void red_add_f32(float* addr, float v) {
    asm volatile("red.global.add.f32 [%0], %1;" :: "l"(addr), "f"(v) : "memory");
}

// ---------------- K2: node projection + dots + zeroing + c_e (fused) --------
__global__ void k_node(const float* __restrict__ nodes,
                       const float* __restrict__ W,
                       const float* __restrict__ a,
                       const float* __restrict__ We) {
    __shared__ float sWt[64 * 65];          // sWt[i*65 + j] = W[j*64 + i]
    __shared__ float sA[192];
    __shared__ float sNode[8][64];

    int tid = threadIdx.x;

    // block 0 computes c_e (fold a_e into W_edge)
    if (blockIdx.x == 0 && tid < 64) {
        int h = tid >> 4, i = tid & 15;
        float acc = 0.f;
#pragma unroll
        for (int f = 0; f < 16; f++)
            acc += a[h * 48 + 32 + f] * We[h * 256 + f * 16 + i];
        ((float*)g_ce4)[tid] = acc;
    }

    for (int idx = tid; idx < 4096; idx += 256) {
        int j = idx >> 6, i = idx & 63;
        sWt[i * 65 + j] = W[idx];
    }
    if (tid < 192) sA[tid] = a[tid];
    __syncthreads();

    int warp = tid >> 5, lane = tid & 31;
    float* wn = (float*)g_Wn;
    float* dS = (float*)g_dotS;
    float* dR = (float*)g_dotR;

    for (int node = blockIdx.x * 8 + warp; node < N_NODES; node += gridDim.x * 8) {
        // zero accumulators for this node (replaces the k_init pass)
        float2* agz = (float2*)(g_aggr + (size_t)node * 16);
        agz[lane] = make_float2(0.f, 0.f);
        if (lane < 4) ((float*)&g_norm[node])[lane] = 0.f;

        const float* nr = nodes + (size_t)node * 64;
        sNode[warp][lane]      = nr[lane];
        sNode[warp][lane + 32] = nr[lane + 32];
        __syncwarp();

        int j0 = lane, j1 = lane + 32;
        float acc0 = 0.f, acc1 = 0.f;
#pragma unroll
        for (int i = 0; i < 64; i++) {
            float nv = sNode[warp][i];
            acc0 += sWt[i * 65 + j0] * nv;
            acc1 += sWt[i * 65 + j1] * nv;
        }
        wn[(size_t)node * 64 + j0] = acc0;
        wn[(size_t)node * 64 + j1] = acc1;

        int h0 = lane >> 4, f = lane & 15;
        int h1 = h0 + 2;
        float ps = acc0 * sA[h0 * 48 + f];
        float pr = acc0 * sA[h0 * 48 + 16 + f];
        float qs = acc1 * sA[h1 * 48 + f];
        float qr = acc1 * sA[h1 * 48 + 16 + f];
#pragma unroll
        for (int m = 8; m >= 1; m >>= 1) {
            ps += __shfl_xor_sync(0xffffffffu, ps, m, 16);
            pr += __shfl_xor_sync(0xffffffffu, pr, m, 16);
            qs += __shfl_xor_sync(0xffffffffu, qs, m, 16);
            qr += __shfl_xor_sync(0xffffffffu, qr, m, 16);
        }
        if (f == 0) {
            dS[node * 4 + h0] = ps;  dS[node * 4 + h1] = qs;
            dR[node * 4 + h0] = pr;  dR[node * 4 + h1] = qr;
        }
        __syncwarp();
    }
}

// ---------------- K3: fused edge pass, 4 edges/warp (2x ILP) -----------------
// 16 lanes per edge-slot; warp handles edges {eb, eb+2} per half. Both edges'
// index/feature loads are issued before any dependent use -> 2 overlapping
// latency chains per warp. Lane sub owns head h=sub>>2, quad q=sub&3.
__global__ void __launch_bounds__(256) k_edge(const float* __restrict__ edges,
                                              const int* __restrict__ recv,
                                              const int* __restrict__ send) {
    int lane = threadIdx.x & 31;
    int sub  = lane & 15;
    int h    = sub >> 2;
    int q    = sub & 3;
    int eb = (blockIdx.x * 8 + (threadIdx.x >> 5)) * 4 + (lane >> 4);
    int e0 = eb, e1 = eb + 2;

    float4 c4 = g_ce4[sub];
    const float* dSf = (const float*)g_dotS;
    const float* dRf = (const float*)g_dotR;

    // ---- front-batched loads for both edges ----
    int s0 = 0, r0 = 0, s1 = 0, r1 = 0;
    float p0 = 0.f, p1 = 0.f;
    bool v0 = e0 < E_TOT, v1 = e1 < E_TOT;

    if (v0) {
        if (e0 < N_EDGES) { s0 = send[e0]; r0 = recv[e0]; }
        else              { s0 = r0 = e0 - N_EDGES; }
    }
    if (v1) {
        if (e1 < N_EDGES) { s1 = send[e1]; r1 = recv[e1]; }
        else              { s1 = r1 = e1 - N_EDGES; }
    }
    if (v0 && e0 < N_EDGES) {
        float4 ef = ((const float4*)edges)[(size_t)e0 * 4 + q];
        p0 = ef.x * c4.x + ef.y * c4.y + ef.z * c4.z + ef.w * c4.w;
    }
    if (v1 && e1 < N_EDGES) {
        float4 ef = ((const float4*)edges)[(size_t)e1 * 4 + q];
        p1 = ef.x * c4.x + ef.y * c4.y + ef.z * c4.z + ef.w * c4.w;
    }

    // quad reduction for both edges
    p0 += __shfl_xor_sync(0xffffffffu, p0, 1, 4);
    p0 += __shfl_xor_sync(0xffffffffu, p0, 2, 4);
    p1 += __shfl_xor_sync(0xffffffffu, p1, 1, 4);
    p1 += __shfl_xor_sync(0xffffffffu, p1, 2, 4);

    // dependent chains, interleaved
    float w0 = 0.f, w1 = 0.f;
    float4 wv0, wv1;
    if (v0) {
        float m = dSf[s0 * 4 + h] + dRf[r0 * 4 + h] + p0;
        w0 = __expf(m > 0.f ? m : 0.01f * m);
        wv0 = g_Wn[(size_t)s0 * 16 + sub];
    }
    if (v1) {
        float m = dSf[s1 * 4 + h] + dRf[r1 * 4 + h] + p1;
        w1 = __expf(m > 0.f ? m : 0.01f * m);
        wv1 = g_Wn[(size_t)s1 * 16 + sub];
    }

    if (v0) {
        if (q == 0) red_add_f32((float*)&g_norm[r0] + h, w0);
        red_add_v4(&g_aggr[(size_t)r0 * 16 + sub],
                   wv0.x * w0, wv0.y * w0, wv0.z * w0, wv0.w * w0);
    }
    if (v1) {
        if (q == 0) red_add_f32((float*)&g_norm[r1] + h, w1);
        red_add_v4(&g_aggr[(size_t)r1 * 16 + sub],
                   wv1.x * w1, wv1.y * w1, wv1.z * w1, wv1.w * w1);
    }
}

// ---------------- K4: normalize + ELU + LayerNorm (float4, 2 nodes/warp) -----
__global__ void k_final(const float* __restrict__ scale,
                        const float* __restrict__ bias,
                        float* __restrict__ out) {
    int lane = threadIdx.x & 31;
    int sub  = lane & 15;
    int node = (blockIdx.x * 8 + (threadIdx.x >> 5)) * 2 + (lane >> 4);
    // N_NODES = 50000 = 3125 blocks * 8 warps * 2 nodes exactly

    float4 ag = g_aggr[(size_t)node * 16 + sub];
    float  nm = ((const float*)&g_norm[node])[sub >> 2];
    float inv_nm = 1.0f / nm;

    float x0 = ag.x * inv_nm, x1 = ag.y * inv_nm;
    float x2 = ag.z * inv_nm, x3 = ag.w * inv_nm;
    float y0 = x0 > 0.f ? x0 : expm1f(x0);
    float y1 = x1 > 0.f ? x1 : expm1f(x1);
    float y2 = x2 > 0.f ? x2 : expm1f(x2);
    float y3 = x3 > 0.f ? x3 : expm1f(x3);

    float sum = y0 + y1 + y2 + y3;
#pragma unroll
    for (int m = 8; m >= 1; m >>= 1) sum += __shfl_xor_sync(0xffffffffu, sum, m, 16);
    float mean = sum * (1.0f / 64.0f);

    float d0 = y0 - mean, d1 = y1 - mean, d2 = y2 - mean, d3 = y3 - mean;
    float v = d0 * d0 + d1 * d1 + d2 * d2 + d3 * d3;
#pragma unroll
    for (int m = 8; m >= 1; m >>= 1) v += __shfl_xor_sync(0xffffffffu, v, m, 16);
    float inv = rsqrtf(v * (1.0f / 64.0f) + 1e-6f);

    float4 sc = ((const float4*)scale)[sub];
    float4 bi = ((const float4*)bias)[sub];
    float4 o;
    o.x = d0 * inv * sc.x + bi.x;
    o.y = d1 * inv * sc.y + bi.y;
    o.z = d2 * inv * sc.z + bi.z;
    o.w = d3 * inv * sc.w + bi.w;
    ((float4*)out)[(size_t)node * 16 + sub] = o;
}

// ---------------- launch -----------------------------------------------------
extern "C" void kernel_launch(void* const* d_in, const int* in_sizes, int n_in,
                              void* d_out, int out_size) {
    const float* nodes   = (const float*)d_in[0];
    const float* edges   = (const float*)d_in[1];
    const int*   recv    = (const int*)d_in[2];
    const int*   send    = (const int*)d_in[3];
    const float* W       = (const float*)d_in[4];
    const float* W_edge  = (const float*)d_in[5];
    const float* a       = (const float*)d_in[6];
    const float* ln_s    = (const float*)d_in[7];
    const float* ln_b    = (const float*)d_in[8];
    float* out = (float*)d_out;

    k_node<<<625, 256>>>(nodes, W, a, W_edge);              // fused: ce + zero + proj + dots
    k_edge<<<(E_TOT + 31) / 32, 256>>>(edges, recv, send);  // 51,563 blocks, 4 edges/warp
    k_final<<<N_NODES / 16, 256>>>(ln_s, ln_b, out);        // 3125 blocks, exact
}

// round 9
// speedup vs baseline: 2.3951x; 1.2311x over previous
#include <cuda_runtime.h>

#define N_NODES 50000
#define N_EDGES 1600000
#define E_TOT   (N_EDGES + N_NODES)

// ---------------- scratch (device globals; no allocation allowed) ----------
__device__ float4 g_Wn[N_NODES * 16];     // projected node features [N,64] as float4
__device__ float4 g_dotS[N_NODES];        // a_s . Wn[n]  per head
__device__ float4 g_dotR[N_NODES];        // a_r . Wn[n]  per head
__device__ float4 g_norm[N_NODES];        // softmax denominator per head
__device__ float4 g_aggr[N_NODES * 16];   // weighted sum [N,64]
__device__ float4 g_ce4[16];              // c_e as float4: g_ce4[h*4+q] = c_h[4q..4q+3]

__device__ __forceinline__ void red_add_v4(float4* addr, float x, float y, float z, float w) {
    asm volatile("red.global.add.v4.f32 [%0], {%1, %2, %3, %4};"
                 :: "l"(addr), "f"(x), "f"(y), "f"(z), "f"(w) : "memory");
}
__device__ __forceinline__ void red_add_f32(float* addr, float v) {
    asm volatile("red.global.add.f32 [%0], %1;" :: "l"(addr), "f"(v) : "memory");
}

// ---------------- K2: tiled GEMM node projection + dots + zero + c_e --------
// Block: 64 nodes x 64 outputs. Thread (jg=t&15, ng=t>>4) computes the 4x4
// tile j in {jg+16jj}, n in {ng+16nn}. Row stride 68 floats (272B = 17*16B):
// float4 LDS phases hit banks jg*4 mod 32 -> conflict-free.
#define NSTR 68
__global__ void __launch_bounds__(256) k_node(const float* __restrict__ nodes,
                                              const float* __restrict__ W,
                                              const float* __restrict__ a,
                                              const float* __restrict__ We) {
    __shared__ __align__(16) float sW[64 * NSTR];
    __shared__ __align__(16) float sN[64 * NSTR];   // input tile, then output tile
    __shared__ float sA[192];

    int tid = threadIdx.x;
    int nb  = blockIdx.x * 64;                      // node base

    if (blockIdx.x == 0 && tid < 64) {              // c_e fold (once)
        int h = tid >> 4, i = tid & 15;
        float acc = 0.f;
#pragma unroll
        for (int f = 0; f < 16; f++)
            acc += a[h * 48 + 32 + f] * We[h * 256 + f * 16 + i];
        ((float*)g_ce4)[tid] = acc;
    }

    // load W [64x64] and node tile [64x64] as float4
    float4 z4 = make_float4(0.f, 0.f, 0.f, 0.f);
#pragma unroll
    for (int g = tid; g < 1024; g += 256) {
        int row = g >> 4, q = g & 15;
        *(float4*)&sW[row * NSTR + q * 4] = ((const float4*)W)[g];
        int node = nb + row;
        *(float4*)&sN[row * NSTR + q * 4] =
            (node < N_NODES) ? ((const float4*)nodes)[(size_t)node * 16 + q] : z4;
        // zero aggr while we're here (same index space)
        if (node < N_NODES) g_aggr[(size_t)node * 16 + q] = z4;
    }
    if (tid < 192) sA[tid] = a[tid];
    if (tid < 64 && nb + tid < N_NODES) g_norm[nb + tid] = z4;
    __syncthreads();

    int jg = tid & 15, ng = tid >> 4;
    float acc[4][4];
#pragma unroll
    for (int nn = 0; nn < 4; nn++)
#pragma unroll
        for (int jj = 0; jj < 4; jj++) acc[nn][jj] = 0.f;

#pragma unroll
    for (int iq = 0; iq < 16; iq++) {
        float4 wv[4], nv[4];
#pragma unroll
        for (int jj = 0; jj < 4; jj++)
            wv[jj] = *(const float4*)&sW[(jg + jj * 16) * NSTR + iq * 4];
#pragma unroll
        for (int nn = 0; nn < 4; nn++)
            nv[nn] = *(const float4*)&sN[(ng + nn * 16) * NSTR + iq * 4];
#pragma unroll
        for (int nn = 0; nn < 4; nn++)
#pragma unroll
            for (int jj = 0; jj < 4; jj++)
                acc[nn][jj] += nv[nn].x * wv[jj].x + nv[nn].y * wv[jj].y
                             + nv[nn].z * wv[jj].z + nv[nn].w * wv[jj].w;
    }
    __syncthreads();

    // stage output tile into sN (overwrites input; sync'd above)
#pragma unroll
    for (int nn = 0; nn < 4; nn++)
#pragma unroll
        for (int jj = 0; jj < 4; jj++)
            sN[(ng + nn * 16) * NSTR + (jg + jj * 16)] = acc[nn][jj];
    __syncthreads();

    // vectorized Wn store
#pragma unroll
    for (int g = tid; g < 1024; g += 256) {
        int row = g >> 4, q = g & 15;
        int node = nb + row;
        if (node < N_NODES)
            g_Wn[(size_t)node * 16 + q] = *(const float4*)&sN[row * NSTR + q * 4];
    }

    // dots: thread = (local node, head); 16 FMAs each, no shuffles
    {
        int n = tid >> 2, h = tid & 3;
        const float* row = &sN[n * NSTR + h * 16];
        float ds = 0.f, dr = 0.f;
#pragma unroll
        for (int f = 0; f < 16; f++) {
            ds += row[f] * sA[h * 48 + f];
            dr += row[f] * sA[h * 48 + 16 + f];
        }
        int node = nb + n;
        if (node < N_NODES) {
            ((float*)g_dotS)[(size_t)node * 4 + h] = ds;
            ((float*)g_dotR)[(size_t)node * 4 + h] = dr;
        }
    }
}

// ---------------- K3: fused edge pass, 4 edges/warp (2x ILP) -----------------
__global__ void __launch_bounds__(256) k_edge(const float* __restrict__ edges,
                                              const int* __restrict__ recv,
                                              const int* __restrict__ send) {
    int lane = threadIdx.x & 31;
    int sub  = lane & 15;
    int h    = sub >> 2;
    int q    = sub & 3;
    int eb = (blockIdx.x * 8 + (threadIdx.x >> 5)) * 4 + (lane >> 4);
    int e0 = eb, e1 = eb + 2;

    float4 c4 = g_ce4[sub];
    const float* dSf = (const float*)g_dotS;
    const float* dRf = (const float*)g_dotR;

    int s0 = 0, r0 = 0, s1 = 0, r1 = 0;
    float p0 = 0.f, p1 = 0.f;
    bool v0 = e0 < E_TOT, v1 = e1 < E_TOT;

    if (v0) {
        if (e0 < N_EDGES) { s0 = send[e0]; r0 = recv[e0]; }
        else              { s0 = r0 = e0 - N_EDGES; }
    }
    if (v1) {
        if (e1 < N_EDGES) { s1 = send[e1]; r1 = recv[e1]; }
        else              { s1 = r1 = e1 - N_EDGES; }
    }
    if (v0 && e0 < N_EDGES) {
        float4 ef = ((const float4*)edges)[(size_t)e0 * 4 + q];
        p0 = ef.x * c4.x + ef.y * c4.y + ef.z * c4.z + ef.w * c4.w;
    }
    if (v1 && e1 < N_EDGES) {
        float4 ef = ((const float4*)edges)[(size_t)e1 * 4 + q];
        p1 = ef.x * c4.x + ef.y * c4.y + ef.z * c4.z + ef.w * c4.w;
    }

    p0 += __shfl_xor_sync(0xffffffffu, p0, 1, 4);
    p0 += __shfl_xor_sync(0xffffffffu, p0, 2, 4);
    p1 += __shfl_xor_sync(0xffffffffu, p1, 1, 4);
    p1 += __shfl_xor_sync(0xffffffffu, p1, 2, 4);

    float w0 = 0.f, w1 = 0.f;
    float4 wv0, wv1;
    if (v0) {
        float m = dSf[s0 * 4 + h] + dRf[r0 * 4 + h] + p0;
        w0 = __expf(m > 0.f ? m : 0.01f * m);
        wv0 = g_Wn[(size_t)s0 * 16 + sub];
    }
    if (v1) {
        float m = dSf[s1 * 4 + h] + dRf[r1 * 4 + h] + p1;
        w1 = __expf(m > 0.f ? m : 0.01f * m);
        wv1 = g_Wn[(size_t)s1 * 16 + sub];
    }

    if (v0) {
        if (q == 0) red_add_f32((float*)&g_norm[r0] + h, w0);
        red_add_v4(&g_aggr[(size_t)r0 * 16 + sub],
                   wv0.x * w0, wv0.y * w0, wv0.z * w0, wv0.w * w0);
    }
    if (v1) {
        if (q == 0) red_add_f32((float*)&g_norm[r1] + h, w1);
        red_add_v4(&g_aggr[(size_t)r1 * 16 + sub],
                   wv1.x * w1, wv1.y * w1, wv1.z * w1, wv1.w * w1);
    }
}

// ---------------- K4: normalize + ELU + LayerNorm (float4, 2 nodes/warp) -----
__global__ void k_final(const float* __restrict__ scale,
                        const float* __restrict__ bias,
                        float* __restrict__ out) {
    int lane = threadIdx.x & 31;
    int sub  = lane & 15;
    int node = (blockIdx.x * 8 + (threadIdx.x >> 5)) * 2 + (lane >> 4);

    float4 ag = g_aggr[(size_t)node * 16 + sub];
    float  nm = ((const float*)&g_norm[node])[sub >> 2];
    float inv_nm = 1.0f / nm;

    float x0 = ag.x * inv_nm, x1 = ag.y * inv_nm;
    float x2 = ag.z * inv_nm, x3 = ag.w * inv_nm;
    float y0 = x0 > 0.f ? x0 : expm1f(x0);
    float y1 = x1 > 0.f ? x1 : expm1f(x1);
    float y2 = x2 > 0.f ? x2 : expm1f(x2);
    float y3 = x3 > 0.f ? x3 : expm1f(x3);

    float sum = y0 + y1 + y2 + y3;
#pragma unroll
    for (int m = 8; m >= 1; m >>= 1) sum += __shfl_xor_sync(0xffffffffu, sum, m, 16);
    float mean = sum * (1.0f / 64.0f);

    float d0 = y0 - mean, d1 = y1 - mean, d2 = y2 - mean, d3 = y3 - mean;
    float v = d0 * d0 + d1 * d1 + d2 * d2 + d3 * d3;
#pragma unroll
    for (int m = 8; m >= 1; m >>= 1) v += __shfl_xor_sync(0xffffffffu, v, m, 16);
    float inv = rsqrtf(v * (1.0f / 64.0f) + 1e-6f);

    float4 sc = ((const float4*)scale)[sub];
    float4 bi = ((const float4*)bias)[sub];
    float4 o;
    o.x = d0 * inv * sc.x + bi.x;
    o.y = d1 * inv * sc.y + bi.y;
    o.z = d2 * inv * sc.z + bi.z;
    o.w = d3 * inv * sc.w + bi.w;
    ((float4*)out)[(size_t)node * 16 + sub] = o;
}

// ---------------- launch -----------------------------------------------------
extern "C" void kernel_launch(void* const* d_in, const int* in_sizes, int n_in,
                              void* d_out, int out_size) {
    const float* nodes   = (const float*)d_in[0];
    const float* edges   = (const float*)d_in[1];
    const int*   recv    = (const int*)d_in[2];
    const int*   send    = (const int*)d_in[3];
    const float* W       = (const float*)d_in[4];
    const float* W_edge  = (const float*)d_in[5];
    const float* a       = (const float*)d_in[6];
    const float* ln_s    = (const float*)d_in[7];
    const float* ln_b    = (const float*)d_in[8];
    float* out = (float*)d_out;

    k_node<<<(N_NODES + 63) / 64, 256>>>(nodes, W, a, W_edge);  // 782 blocks
    k_edge<<<(E_TOT + 31) / 32, 256>>>(edges, recv, send);      // 51,563 blocks
    k_final<<<N_NODES / 16, 256>>>(ln_s, ln_b, out);            // 3125 blocks, exact
}

// round 10
// speedup vs baseline: 2.4377x; 1.0178x over previous
#include <cuda_runtime.h>
#include <cuda_fp16.h>

#define N_NODES 50000
#define N_EDGES 1600000

// ---------------- scratch (device globals; no allocation allowed) ----------
__device__ uint2  g_WnH[N_NODES * 16];    // projected node features fp16: node*16+q holds halves [4q..4q+3]
__device__ float4 g_dotS[N_NODES];        // a_s . Wn[n]  per head (fp32)
__device__ float4 g_dotR[N_NODES];        // a_r . Wn[n]  per head (fp32)
__device__ float4 g_norm[N_NODES];        // softmax denominator per head (excl. self edge)
__device__ float4 g_aggr[N_NODES * 16];   // weighted sum [N,64] (excl. self edge)
__device__ float4 g_ce4[16];              // c_e as float4: g_ce4[h*4+q] = c_h[4q..4q+3]

__device__ __forceinline__ void red_add_v4(float4* addr, float x, float y, float z, float w) {
    asm volatile("red.global.add.v4.f32 [%0], {%1, %2, %3, %4};"
                 :: "l"(addr), "f"(x), "f"(y), "f"(z), "f"(w) : "memory");
}
__device__ __forceinline__ void red_add_f32(float* addr, float v) {
    asm volatile("red.global.add.f32 [%0], %1;" :: "l"(addr), "f"(v) : "memory");
}

// ---------------- K2: tiled GEMM node projection + dots + zero + c_e --------
#define NSTR 68
__global__ void __launch_bounds__(256) k_node(const float* __restrict__ nodes,
                                              const float* __restrict__ W,
                                              const float* __restrict__ a,
                                              const float* __restrict__ We) {
    __shared__ __align__(16) float sW[64 * NSTR];
    __shared__ __align__(16) float sN[64 * NSTR];   // input tile, then output tile
    __shared__ float sA[192];

    int tid = threadIdx.x;
    int nb  = blockIdx.x * 64;

    if (blockIdx.x == 0 && tid < 64) {              // c_e fold (once)
        int h = tid >> 4, i = tid & 15;
        float acc = 0.f;
#pragma unroll
        for (int f = 0; f < 16; f++)
            acc += a[h * 48 + 32 + f] * We[h * 256 + f * 16 + i];
        ((float*)g_ce4)[tid] = acc;
    }

    float4 z4 = make_float4(0.f, 0.f, 0.f, 0.f);
#pragma unroll
    for (int g = tid; g < 1024; g += 256) {
        int row = g >> 4, q = g & 15;
        *(float4*)&sW[row * NSTR + q * 4] = ((const float4*)W)[g];
        int node = nb + row;
        *(float4*)&sN[row * NSTR + q * 4] =
            (node < N_NODES) ? ((const float4*)nodes)[(size_t)node * 16 + q] : z4;
        if (node < N_NODES) g_aggr[(size_t)node * 16 + q] = z4;
    }
    if (tid < 192) sA[tid] = a[tid];
    if (tid < 64 && nb + tid < N_NODES) g_norm[nb + tid] = z4;
    __syncthreads();

    int jg = tid & 15, ng = tid >> 4;
    float acc[4][4];
#pragma unroll
    for (int nn = 0; nn < 4; nn++)
#pragma unroll
        for (int jj = 0; jj < 4; jj++) acc[nn][jj] = 0.f;

#pragma unroll
    for (int iq = 0; iq < 16; iq++) {
        float4 wv[4], nv[4];
#pragma unroll
        for (int jj = 0; jj < 4; jj++)
            wv[jj] = *(const float4*)&sW[(jg + jj * 16) * NSTR + iq * 4];
#pragma unroll
        for (int nn = 0; nn < 4; nn++)
            nv[nn] = *(const float4*)&sN[(ng + nn * 16) * NSTR + iq * 4];
#pragma unroll
        for (int nn = 0; nn < 4; nn++)
#pragma unroll
            for (int jj = 0; jj < 4; jj++)
                acc[nn][jj] += nv[nn].x * wv[jj].x + nv[nn].y * wv[jj].y
                             + nv[nn].z * wv[jj].z + nv[nn].w * wv[jj].w;
    }
    __syncthreads();

#pragma unroll
    for (int nn = 0; nn < 4; nn++)
#pragma unroll
        for (int jj = 0; jj < 4; jj++)
            sN[(ng + nn * 16) * NSTR + (jg + jj * 16)] = acc[nn][jj];
    __syncthreads();

    // fp16 Wn store (half the bytes of the old fp32 pass)
#pragma unroll
    for (int g = tid; g < 1024; g += 256) {
        int row = g >> 4, q = g & 15;
        int node = nb + row;
        if (node < N_NODES) {
            float4 v = *(const float4*)&sN[row * NSTR + q * 4];
            __half2 h0 = __floats2half2_rn(v.x, v.y);
            __half2 h1 = __floats2half2_rn(v.z, v.w);
            uint2 pk;
            pk.x = *(unsigned*)&h0;
            pk.y = *(unsigned*)&h1;
            g_WnH[(size_t)node * 16 + q] = pk;
        }
    }

    // dots from fp32 smem tile: thread = (local node, head)
    {
        int n = tid >> 2, h = tid & 3;
        const float* row = &sN[n * NSTR + h * 16];
        float ds = 0.f, dr = 0.f;
#pragma unroll
        for (int f = 0; f < 16; f++) {
            ds += row[f] * sA[h * 48 + f];
            dr += row[f] * sA[h * 48 + 16 + f];
        }
        int node = nb + n;
        if (node < N_NODES) {
            ((float*)g_dotS)[(size_t)node * 4 + h] = ds;
            ((float*)g_dotR)[(size_t)node * 4 + h] = dr;
        }
    }
}

// ---------------- K3: fused edge pass, real edges only, 4 edges/warp ---------
// 1.6M edges = 50000 blocks * 8 warps * 4 edges exactly: no branches at all.
__global__ void __launch_bounds__(256) k_edge(const float* __restrict__ edges,
                                              const int* __restrict__ recv,
                                              const int* __restrict__ send) {
    int lane = threadIdx.x & 31;
    int sub  = lane & 15;
    int h    = sub >> 2;
    int q    = sub & 3;
    int eb = (blockIdx.x * 8 + (threadIdx.x >> 5)) * 4 + (lane >> 4);
    int e0 = eb, e1 = eb + 2;

    float4 c4 = g_ce4[sub];
    const float* dSf = (const float*)g_dotS;
    const float* dRf = (const float*)g_dotR;

    // front-batched loads for both edges
    int s0 = send[e0], r0 = recv[e0];
    int s1 = send[e1], r1 = recv[e1];
    float4 ef0 = ((const float4*)edges)[(size_t)e0 * 4 + q];
    float4 ef1 = ((const float4*)edges)[(size_t)e1 * 4 + q];

    float p0 = ef0.x * c4.x + ef0.y * c4.y + ef0.z * c4.z + ef0.w * c4.w;
    float p1 = ef1.x * c4.x + ef1.y * c4.y + ef1.z * c4.z + ef1.w * c4.w;
    p0 += __shfl_xor_sync(0xffffffffu, p0, 1, 4);
    p0 += __shfl_xor_sync(0xffffffffu, p0, 2, 4);
    p1 += __shfl_xor_sync(0xffffffffu, p1, 1, 4);
    p1 += __shfl_xor_sync(0xffffffffu, p1, 2, 4);

    float m0 = dSf[s0 * 4 + h] + dRf[r0 * 4 + h] + p0;
    float m1 = dSf[s1 * 4 + h] + dRf[r1 * 4 + h] + p1;
    float w0 = __expf(m0 > 0.f ? m0 : 0.01f * m0);
    float w1 = __expf(m1 > 0.f ? m1 : 0.01f * m1);

    uint2 pk0 = g_WnH[(size_t)s0 * 16 + sub];    // fp16 gather: 1 line/edge
    uint2 pk1 = g_WnH[(size_t)s1 * 16 + sub];

    if (q == 0) red_add_f32((float*)&g_norm[r0] + h, w0);
    if (q == 0) red_add_f32((float*)&g_norm[r1] + h, w1);

    float2 a0 = __half22float2(*(__half2*)&pk0.x);
    float2 b0 = __half22float2(*(__half2*)&pk0.y);
    red_add_v4(&g_aggr[(size_t)r0 * 16 + sub],
               a0.x * w0, a0.y * w0, b0.x * w0, b0.y * w0);

    float2 a1 = __half22float2(*(__half2*)&pk1.x);
    float2 b1 = __half22float2(*(__half2*)&pk1.y);
    red_add_v4(&g_aggr[(size_t)r1 * 16 + sub],
               a1.x * w1, a1.y * w1, b1.x * w1, b1.y * w1);
}

// ---------------- K4: self-edge + normalize + ELU + LayerNorm ----------------
__global__ void k_final(const float* __restrict__ scale,
                        const float* __restrict__ bias,
                        float* __restrict__ out) {
    int lane = threadIdx.x & 31;
    int sub  = lane & 15;
    int h    = sub >> 2;
    int node = (blockIdx.x * 8 + (threadIdx.x >> 5)) * 2 + (lane >> 4);
    // N_NODES = 50000 = 3125 blocks * 8 warps * 2 nodes exactly

    // self edge: weight exp(leaky(dS+dR)), message = Wn[node]
    float ms = ((const float*)g_dotS)[(size_t)node * 4 + h]
             + ((const float*)g_dotR)[(size_t)node * 4 + h];
    float ws = __expf(ms > 0.f ? ms : 0.01f * ms);

    uint2 pk = g_WnH[(size_t)node * 16 + sub];
    float2 va = __half22float2(*(__half2*)&pk.x);
    float2 vb = __half22float2(*(__half2*)&pk.y);

    float4 ag = g_aggr[(size_t)node * 16 + sub];
    float  nm = ((const float*)&g_norm[node])[h] + ws;
    float inv_nm = 1.0f / nm;

    float x0 = (ag.x + ws * va.x) * inv_nm;
    float x1 = (ag.y + ws * va.y) * inv_nm;
    float x2 = (ag.z + ws * vb.x) * inv_nm;
    float x3 = (ag.w + ws * vb.y) * inv_nm;
    float y0 = x0 > 0.f ? x0 : expm1f(x0);
    float y1 = x1 > 0.f ? x1 : expm1f(x1);
    float y2 = x2 > 0.f ? x2 : expm1f(x2);
    float y3 = x3 > 0.f ? x3 : expm1f(x3);

    float sum = y0 + y1 + y2 + y3;
#pragma unroll
    for (int m = 8; m >= 1; m >>= 1) sum += __shfl_xor_sync(0xffffffffu, sum, m, 16);
    float mean = sum * (1.0f / 64.0f);

    float d0 = y0 - mean, d1 = y1 - mean, d2 = y2 - mean, d3 = y3 - mean;
    float v = d0 * d0 + d1 * d1 + d2 * d2 + d3 * d3;
#pragma unroll
    for (int m = 8; m >= 1; m >>= 1) v += __shfl_xor_sync(0xffffffffu, v, m, 16);
    float inv = rsqrtf(v * (1.0f / 64.0f) + 1e-6f);

    float4 sc = ((const float4*)scale)[sub];
    float4 bi = ((const float4*)bias)[sub];
    float4 o;
    o.x = d0 * inv * sc.x + bi.x;
    o.y = d1 * inv * sc.y + bi.y;
    o.z = d2 * inv * sc.z + bi.z;
    o.w = d3 * inv * sc.w + bi.w;
    ((float4*)out)[(size_t)node * 16 + sub] = o;
}

// ---------------- launch -----------------------------------------------------
extern "C" void kernel_launch(void* const* d_in, const int* in_sizes, int n_in,
                              void* d_out, int out_size) {
    const float* nodes   = (const float*)d_in[0];
    const float* edges   = (const float*)d_in[1];
    const int*   recv    = (const int*)d_in[2];
    const int*   send    = (const int*)d_in[3];
    const float* W       = (const float*)d_in[4];
    const float* W_edge  = (const float*)d_in[5];
    const float* a       = (const float*)d_in[6];
    const float* ln_s    = (const float*)d_in[7];
    const float* ln_b    = (const float*)d_in[8];
    float* out = (float*)d_out;

    k_node<<<(N_NODES + 63) / 64, 256>>>(nodes, W, a, W_edge);  // 782 blocks
    k_edge<<<N_EDGES / 32, 256>>>(edges, recv, send);           // 50,000 blocks, exact
    k_final<<<N_NODES / 16, 256>>>(ln_s, ln_b, out);            // 3125 blocks, exact
}

// round 11
// speedup vs baseline: 2.7411x; 1.1244x over previous
#include <cuda_runtime.h>
#include <cuda_fp16.h>

#define N_NODES 50000
#define N_EDGES 1600000

// ---------------- scratch (device globals; no allocation allowed) ----------
__device__ uint2  g_WnH[N_NODES * 16];    // projected node features fp16: node*16+q holds halves [4q..4q+3]
__device__ float4 g_dotS[N_NODES];        // a_s . Wn[n]  per head (fp32)
__device__ float4 g_dotR[N_NODES];        // a_r . Wn[n]  per head (fp32)
__device__ float4 g_norm[N_NODES];        // softmax denominator per head (excl. self edge)
__device__ float4 g_aggr[N_NODES * 16];   // weighted sum [N,64] (excl. self edge)
__device__ float4 g_ce4[16];              // c_e as float4: g_ce4[h*4+q] = c_h[4q..4q+3]

__device__ __forceinline__ void red_add_v4(float4* addr, float x, float y, float z, float w) {
    asm volatile("red.global.add.v4.f32 [%0], {%1, %2, %3, %4};"
                 :: "l"(addr), "f"(x), "f"(y), "f"(z), "f"(w) : "memory");
}
__device__ __forceinline__ void red_add_f32(float* addr, float v) {
    asm volatile("red.global.add.f32 [%0], %1;" :: "l"(addr), "f"(v) : "memory");
}

// ---------------- K2: tiled GEMM node projection + dots + zero + c_e --------
#define NSTR 68
__global__ void __launch_bounds__(256) k_node(const float* __restrict__ nodes,
                                              const float* __restrict__ W,
                                              const float* __restrict__ a,
                                              const float* __restrict__ We) {
    __shared__ __align__(16) float sW[64 * NSTR];
    __shared__ __align__(16) float sN[64 * NSTR];   // input tile, then output tile
    __shared__ float sA[192];

    int tid = threadIdx.x;
    int nb  = blockIdx.x * 64;

    if (blockIdx.x == 0 && tid < 64) {              // c_e fold (once)
        int h = tid >> 4, i = tid & 15;
        float acc = 0.f;
#pragma unroll
        for (int f = 0; f < 16; f++)
            acc += a[h * 48 + 32 + f] * We[h * 256 + f * 16 + i];
        ((float*)g_ce4)[tid] = acc;
    }

    float4 z4 = make_float4(0.f, 0.f, 0.f, 0.f);
#pragma unroll
    for (int g = tid; g < 1024; g += 256) {
        int row = g >> 4, q = g & 15;
        *(float4*)&sW[row * NSTR + q * 4] = ((const float4*)W)[g];
        int node = nb + row;
        *(float4*)&sN[row * NSTR + q * 4] =
            (node < N_NODES) ? ((const float4*)nodes)[(size_t)node * 16 + q] : z4;
        if (node < N_NODES) g_aggr[(size_t)node * 16 + q] = z4;
    }
    if (tid < 192) sA[tid] = a[tid];
    if (tid < 64 && nb + tid < N_NODES) g_norm[nb + tid] = z4;
    __syncthreads();

    int jg = tid & 15, ng = tid >> 4;
    float acc[4][4];
#pragma unroll
    for (int nn = 0; nn < 4; nn++)
#pragma unroll
        for (int jj = 0; jj < 4; jj++) acc[nn][jj] = 0.f;

#pragma unroll
    for (int iq = 0; iq < 16; iq++) {
        float4 wv[4], nv[4];
#pragma unroll
        for (int jj = 0; jj < 4; jj++)
            wv[jj] = *(const float4*)&sW[(jg + jj * 16) * NSTR + iq * 4];
#pragma unroll
        for (int nn = 0; nn < 4; nn++)
            nv[nn] = *(const float4*)&sN[(ng + nn * 16) * NSTR + iq * 4];
#pragma unroll
        for (int nn = 0; nn < 4; nn++)
#pragma unroll
            for (int jj = 0; jj < 4; jj++)
                acc[nn][jj] += nv[nn].x * wv[jj].x + nv[nn].y * wv[jj].y
                             + nv[nn].z * wv[jj].z + nv[nn].w * wv[jj].w;
    }
    __syncthreads();

#pragma unroll
    for (int nn = 0; nn < 4; nn++)
#pragma unroll
        for (int jj = 0; jj < 4; jj++)
            sN[(ng + nn * 16) * NSTR + (jg + jj * 16)] = acc[nn][jj];
    __syncthreads();

    // fp16 Wn store
#pragma unroll
    for (int g = tid; g < 1024; g += 256) {
        int row = g >> 4, q = g & 15;
        int node = nb + row;
        if (node < N_NODES) {
            float4 v = *(const float4*)&sN[row * NSTR + q * 4];
            __half2 h0 = __floats2half2_rn(v.x, v.y);
            __half2 h1 = __floats2half2_rn(v.z, v.w);
            uint2 pk;
            pk.x = *(unsigned*)&h0;
            pk.y = *(unsigned*)&h1;
            g_WnH[(size_t)node * 16 + q] = pk;
        }
    }

    // dots from fp32 smem tile: thread = (local node, head)
    {
        int n = tid >> 2, h = tid & 3;
        const float* row = &sN[n * NSTR + h * 16];
        float ds = 0.f, dr = 0.f;
#pragma unroll
        for (int f = 0; f < 16; f++) {
            ds += row[f] * sA[h * 48 + f];
            dr += row[f] * sA[h * 48 + 16 + f];
        }
        int node = nb + n;
        if (node < N_NODES) {
            ((float*)g_dotS)[(size_t)node * 4 + h] = ds;
            ((float*)g_dotR)[(size_t)node * 4 + h] = dr;
        }
    }
}

// ---------------- K3: fused edge pass, 8 edges/warp (4x ILP) -----------------
// 16 lanes per edge-slot; each 16-lane group handles 4 edges with strictly
// stage-batched loads: 4 independent latency chains in flight per group.
// 1.6M edges = 25,000 blocks * 8 warps * 8 edges exactly: no bounds checks.
__global__ void __launch_bounds__(256) k_edge(const float* __restrict__ edges,
                                              const int* __restrict__ recv,
                                              const int* __restrict__ send) {
    int lane = threadIdx.x & 31;
    int sub  = lane & 15;
    int h    = sub >> 2;
    int q    = sub & 3;
    int base = (blockIdx.x * 8 + (threadIdx.x >> 5)) * 8 + (lane >> 4);

    float4 c4 = g_ce4[sub];
    const float* dSf = (const float*)g_dotS;
    const float* dRf = (const float*)g_dotR;

    // stage 1: all index loads
    int s[4], r[4];
#pragma unroll
    for (int k = 0; k < 4; k++) {
        int e = base + 2 * k;
        s[k] = send[e];
        r[k] = recv[e];
    }

    // stage 2: all edge-feature loads + partial dots
    float p[4];
#pragma unroll
    for (int k = 0; k < 4; k++) {
        float4 ef = ((const float4*)edges)[(size_t)(base + 2 * k) * 4 + q];
        p[k] = ef.x * c4.x + ef.y * c4.y + ef.z * c4.z + ef.w * c4.w;
    }
#pragma unroll
    for (int k = 0; k < 4; k++) {
        p[k] += __shfl_xor_sync(0xffffffffu, p[k], 1, 4);
        p[k] += __shfl_xor_sync(0xffffffffu, p[k], 2, 4);
    }

    // stage 3: all dot loads (batched before use)
    float dsv[4], drv[4];
#pragma unroll
    for (int k = 0; k < 4; k++) dsv[k] = dSf[(size_t)s[k] * 4 + h];
#pragma unroll
    for (int k = 0; k < 4; k++) drv[k] = dRf[(size_t)r[k] * 4 + h];

    // stage 4: all Wn gathers (batched)
    uint2 pk[4];
#pragma unroll
    for (int k = 0; k < 4; k++) pk[k] = g_WnH[(size_t)s[k] * 16 + sub];

    // stage 5: weights
    float w[4];
#pragma unroll
    for (int k = 0; k < 4; k++) {
        float m = dsv[k] + drv[k] + p[k];
        w[k] = __expf(m > 0.f ? m : 0.01f * m);
    }

    // stage 6: reductions
#pragma unroll
    for (int k = 0; k < 4; k++) {
        if (q == 0) red_add_f32((float*)&g_norm[r[k]] + h, w[k]);
        float2 va = __half22float2(*(__half2*)&pk[k].x);
        float2 vb = __half22float2(*(__half2*)&pk[k].y);
        red_add_v4(&g_aggr[(size_t)r[k] * 16 + sub],
                   va.x * w[k], va.y * w[k], vb.x * w[k], vb.y * w[k]);
    }
}

// ---------------- K4: self-edge + normalize + ELU + LayerNorm ----------------
__global__ void k_final(const float* __restrict__ scale,
                        const float* __restrict__ bias,
                        float* __restrict__ out) {
    int lane = threadIdx.x & 31;
    int sub  = lane & 15;
    int h    = sub >> 2;
    int node = (blockIdx.x * 8 + (threadIdx.x >> 5)) * 2 + (lane >> 4);

    float ms = ((const float*)g_dotS)[(size_t)node * 4 + h]
             + ((const float*)g_dotR)[(size_t)node * 4 + h];
    float ws = __expf(ms > 0.f ? ms : 0.01f * ms);

    uint2 pk = g_WnH[(size_t)node * 16 + sub];
    float2 va = __half22float2(*(__half2*)&pk.x);
    float2 vb = __half22float2(*(__half2*)&pk.y);

    float4 ag = g_aggr[(size_t)node * 16 + sub];
    float  nm = ((const float*)&g_norm[node])[h] + ws;
    float inv_nm = 1.0f / nm;

    float x0 = (ag.x + ws * va.x) * inv_nm;
    float x1 = (ag.y + ws * va.y) * inv_nm;
    float x2 = (ag.z + ws * vb.x) * inv_nm;
    float x3 = (ag.w + ws * vb.y) * inv_nm;
    float y0 = x0 > 0.f ? x0 : expm1f(x0);
    float y1 = x1 > 0.f ? x1 : expm1f(x1);
    float y2 = x2 > 0.f ? x2 : expm1f(x2);
    float y3 = x3 > 0.f ? x3 : expm1f(x3);

    float sum = y0 + y1 + y2 + y3;
#pragma unroll
    for (int m = 8; m >= 1; m >>= 1) sum += __shfl_xor_sync(0xffffffffu, sum, m, 16);
    float mean = sum * (1.0f / 64.0f);

    float d0 = y0 - mean, d1 = y1 - mean, d2 = y2 - mean, d3 = y3 - mean;
    float v = d0 * d0 + d1 * d1 + d2 * d2 + d3 * d3;
#pragma unroll
    for (int m = 8; m >= 1; m >>= 1) v += __shfl_xor_sync(0xffffffffu, v, m, 16);
    float inv = rsqrtf(v * (1.0f / 64.0f) + 1e-6f);

    float4 sc = ((const float4*)scale)[sub];
    float4 bi = ((const float4*)bias)[sub];
    float4 o;
    o.x = d0 * inv * sc.x + bi.x;
    o.y = d1 * inv * sc.y + bi.y;
    o.z = d2 * inv * sc.z + bi.z;
    o.w = d3 * inv * sc.w + bi.w;
    ((float4*)out)[(size_t)node * 16 + sub] = o;
}

// ---------------- launch -----------------------------------------------------
extern "C" void kernel_launch(void* const* d_in, const int* in_sizes, int n_in,
                              void* d_out, int out_size) {
    const float* nodes   = (const float*)d_in[0];
    const float* edges   = (const float*)d_in[1];
    const int*   recv    = (const int*)d_in[2];
    const int*   send    = (const int*)d_in[3];
    const float* W       = (const float*)d_in[4];
    const float* W_edge  = (const float*)d_in[5];
    const float* a       = (const float*)d_in[6];
    const float* ln_s    = (const float*)d_in[7];
    const float* ln_b    = (const float*)d_in[8];
    float* out = (float*)d_out;

    k_node<<<(N_NODES + 63) / 64, 256>>>(nodes, W, a, W_edge);  // 782 blocks
    k_edge<<<N_EDGES / 64, 256>>>(edges, recv, send);           // 25,000 blocks, 8 edges/warp
    k_final<<<N_NODES / 16, 256>>>(ln_s, ln_b, out);            // 3125 blocks, exact
}